// round 2
// baseline (speedup 1.0000x reference)
#include <cuda_runtime.h>
#include <cstdint>

// Problem constants (fixed by the reference)
#define B_DIM 2048
#define N_DIM 512
#define C_DIM 64
#define L_DIM 2
#define O_DIM 8192
#define LO (L_DIM * O_DIM)      // 16384
#define LO4 (LO / 4)            // 4096 (power of 2)

// Scratch: selection table sel[l*O + o] = input-feature index (0..N-1)
__device__ int g_sel[LO];

// Kernel 1: argmax over candidates (first-max wins, matching jnp.argmax),
// then gather the index table entry. NOTE: indices land as int32 (JAX
// without x64 downcasts int64 -> int32).
__global__ void build_sel_kernel(const float* __restrict__ w,
                                 const int* __restrict__ idx) {
    int lo = blockIdx.x * blockDim.x + threadIdx.x;
    if (lo >= LO) return;
    float best = w[lo];
    int bc = 0;
#pragma unroll
    for (int c = 1; c < C_DIM; ++c) {
        float v = w[c * LO + lo];
        if (v > best) { best = v; bc = c; }
    }
    g_sel[lo] = idx[bc * LO + lo];
}

// Kernel 2: out[b, lo] = x[b, sel[lo]], vectorized as float4 stores.
// Threads with the same b are contiguous (4096 per b), so the random
// gathers from x land in a 2KB row -> L1/L2 resident. sel reads coalesced.
__global__ void __launch_bounds__(256) gather_kernel(
    const float* __restrict__ x, float4* __restrict__ out) {
    int i = blockIdx.x * blockDim.x + threadIdx.x;   // [0, B*LO4)
    int lo4 = i & (LO4 - 1);
    int b = i >> 12;                                  // / LO4
    int4 s = ((const int4*)g_sel)[lo4];
    const float* __restrict__ xr = x + (size_t)b * N_DIM;
    float4 v;
    v.x = __ldg(xr + s.x);
    v.y = __ldg(xr + s.y);
    v.z = __ldg(xr + s.z);
    v.w = __ldg(xr + s.w);
    out[i] = v;
}

extern "C" void kernel_launch(void* const* d_in, const int* in_sizes, int n_in,
                              void* d_out, int out_size) {
    const float* x   = (const float*)d_in[0];
    const float* w   = (const float*)d_in[1];
    const int*   idx = (const int*)d_in[2];
    float4* out = (float4*)d_out;

    build_sel_kernel<<<(LO + 255) / 256, 256>>>(w, idx);

    int total4 = B_DIM * LO4;                         // 8,388,608
    gather_kernel<<<total4 / 256, 256>>>(x, out);
}

// round 3
// speedup vs baseline: 1.3012x; 1.3012x over previous
#include <cuda_runtime.h>
#include <cstdint>

// Problem constants (fixed by the reference)
#define B_DIM 2048
#define N_DIM 512
#define C_DIM 64
#define L_DIM 2
#define O_DIM 8192
#define LO (L_DIM * O_DIM)      // 16384
#define LO4 (LO / 4)            // 4096 float4 per batch row
#define SPLIT 2                 // blocks per batch row
#define CHUNK4 (LO4 / SPLIT)    // 2048 float4 per block
#define ITERS (CHUNK4 / 256)    // 8 iterations per thread

// Scratch: selection table sel[l*O + o] = input-feature index (0..N-1)
__device__ int g_sel[LO];

// Kernel 1: argmax over candidates (first-max wins, matching jnp.argmax),
// then gather the index table entry (int32 on device).
__global__ void build_sel_kernel(const float* __restrict__ w,
                                 const int* __restrict__ idx) {
    int lo = blockIdx.x * blockDim.x + threadIdx.x;
    if (lo >= LO) return;
    float best = w[lo];
    int bc = 0;
#pragma unroll
    for (int c = 1; c < C_DIM; ++c) {
        float v = w[c * LO + lo];
        if (v > best) { best = v; bc = c; }
    }
    g_sel[lo] = idx[bc * LO + lo];
}

// Kernel 2: out[b, lo] = x[b, sel[lo]].
// Each block stages x[b,:] (2KB) in shared memory, then gathers via LDS
// (smem crossbar, ~3-4 way random bank conflicts) instead of hammering
// L1tex with scattered LDG wavefronts. Stores are fully-coalesced float4.
__global__ void __launch_bounds__(256) gather_kernel(
    const float* __restrict__ x, float4* __restrict__ out) {
    __shared__ float xs[N_DIM];

    int b     = blockIdx.x >> 1;          // / SPLIT
    int chunk = blockIdx.x & (SPLIT - 1);

    // cooperative row load: 256 threads x float2 = 512 floats
    ((float2*)xs)[threadIdx.x] = ((const float2*)(x + (size_t)b * N_DIM))[threadIdx.x];
    __syncthreads();

    const int4*  sel4 = (const int4*)g_sel + chunk * CHUNK4;
    float4*      ob   = out + (size_t)b * LO4 + chunk * CHUNK4;

#pragma unroll
    for (int it = 0; it < ITERS; ++it) {
        int i = it * 256 + threadIdx.x;
        int4 s = __ldg(sel4 + i);
        float4 v;
        v.x = xs[s.x];
        v.y = xs[s.y];
        v.z = xs[s.z];
        v.w = xs[s.w];
        ob[i] = v;
    }
}

extern "C" void kernel_launch(void* const* d_in, const int* in_sizes, int n_in,
                              void* d_out, int out_size) {
    const float* x   = (const float*)d_in[0];
    const float* w   = (const float*)d_in[1];
    const int*   idx = (const int*)d_in[2];
    float4* out = (float4*)d_out;

    build_sel_kernel<<<(LO + 255) / 256, 256>>>(w, idx);
    gather_kernel<<<B_DIM * SPLIT, 256>>>(x, out);
}